// round 3
// baseline (speedup 1.0000x reference)
#include <cuda_runtime.h>

#define N_NODES_C 100000
#define N_EDGES_C 50000
#define NNZ_CAP   1600000
#define F1 128
#define F2 16
#define SCAN_B 512
#define NB_NODES ((N_NODES_C + SCAN_B - 1) / SCAN_B)   // 196
#define NB_EDGES ((N_EDGES_C + SCAN_B - 1) / SCAN_B)   // 98

// ---------------- static scratch (no cudaMalloc anywhere) ----------------
__device__ int   g_idx64;                      // 1 = indices are int64
__device__ int   g_ncnt[N_NODES_C];
__device__ int   g_ecnt[N_EDGES_C];
__device__ int   g_noff[N_NODES_C + 1];
__device__ int   g_eoff[N_EDGES_C + 1];
__device__ int   g_ncur[N_NODES_C];
__device__ int   g_ecur[N_EDGES_C];
__device__ int   g_bsums[SCAN_B + 1];
__device__ float g_dinv[N_NODES_C];
__device__ float g_binv[N_EDGES_C];
__device__ int   g_e_members[NNZ_CAP];         // node ids grouped by edge
__device__ int   g_n_members[NNZ_CAP];         // edge ids grouped by node
__device__ __align__(16) float g_xw[(size_t)N_NODES_C * F1];
__device__ __align__(16) float g_efeat[(size_t)N_EDGES_C * F1];
__device__ __align__(16) float g_h[(size_t)N_NODES_C * F1];
__device__ __align__(16) float g_hw[(size_t)N_NODES_C * F2];
__device__ __align__(16) float g_efeat2[(size_t)N_EDGES_C * F2];

// ---------------- index dtype handling ----------------
__global__ void detect_kernel(const void* ni, int nnz) {
    __shared__ int bad_s;
    if (threadIdx.x == 0) bad_s = 0;
    __syncthreads();
    int k = nnz < 64 ? nnz : 64;
    if ((int)threadIdx.x < k) {
        long long v = ((const long long*)ni)[threadIdx.x];
        if (v < 0 || v >= (1LL << 31)) atomicOr(&bad_s, 1);
    }
    __syncthreads();
    if (threadIdx.x == 0) g_idx64 = bad_s ? 0 : 1;
}

__device__ __forceinline__ int load_idx(const void* p, int i, int is64) {
    return is64 ? (int)((const long long*)p)[i] : ((const int*)p)[i];
}

// ---------------- counting / CSR build ----------------
__global__ void zero_cnt_kernel() {
    int i = blockIdx.x * blockDim.x + threadIdx.x;
    if (i < N_NODES_C) g_ncnt[i] = 0;
    if (i < N_EDGES_C) g_ecnt[i] = 0;
}

__global__ void hist_kernel(const void* ni, const void* ei, int nnz) {
    int i = blockIdx.x * blockDim.x + threadIdx.x;
    if (i >= nnz) return;
    int is64 = g_idx64;
    atomicAdd(&g_ncnt[load_idx(ni, i, is64)], 1);
    atomicAdd(&g_ecnt[load_idx(ei, i, is64)], 1);
}

__global__ void block_sums_kernel(const int* __restrict__ cnt, int n, int* __restrict__ bsums) {
    __shared__ int s[SCAN_B];
    int i = blockIdx.x * SCAN_B + threadIdx.x;
    s[threadIdx.x] = (i < n) ? cnt[i] : 0;
    __syncthreads();
    for (int d = SCAN_B / 2; d > 0; d >>= 1) {
        if (threadIdx.x < d) s[threadIdx.x] += s[threadIdx.x + d];
        __syncthreads();
    }
    if (threadIdx.x == 0) bsums[blockIdx.x] = s[0];
}

__global__ void scan_bsums_kernel(int* __restrict__ b, int nb) {
    __shared__ int s[SCAN_B];
    int tid = threadIdx.x;
    int v = (tid < nb) ? b[tid] : 0;
    s[tid] = v;
    __syncthreads();
    for (int d = 1; d < SCAN_B; d <<= 1) {
        int t = (tid >= d) ? s[tid - d] : 0;
        __syncthreads();
        s[tid] += t;
        __syncthreads();
    }
    if (tid < nb) b[tid] = s[tid] - v;           // exclusive
    if (tid == nb - 1) b[nb] = s[tid];           // total
}

__global__ void scan_apply_kernel(const int* __restrict__ cnt, int n,
                                  const int* __restrict__ bsums, int* __restrict__ off) {
    __shared__ int s[SCAN_B];
    int tid = threadIdx.x;
    int i = blockIdx.x * SCAN_B + tid;
    int v = (i < n) ? cnt[i] : 0;
    s[tid] = v;
    __syncthreads();
    for (int d = 1; d < SCAN_B; d <<= 1) {
        int t = (tid >= d) ? s[tid - d] : 0;
        __syncthreads();
        s[tid] += t;
        __syncthreads();
    }
    int base = bsums[blockIdx.x];
    if (i < n) off[i] = base + s[tid] - v;
    if (i == n - 1) off[n] = base + s[tid];
}

__global__ void prep_kernel() {
    int i = blockIdx.x * blockDim.x + threadIdx.x;
    if (i < N_EDGES_C) {
        int d = g_eoff[i + 1] - g_eoff[i];
        g_binv[i] = d > 0 ? 1.f / (float)d : 0.f;
        g_ecur[i] = g_eoff[i];
    }
    if (i < N_NODES_C) {
        int d = g_noff[i + 1] - g_noff[i];
        g_dinv[i] = d > 0 ? 1.f / (float)d : 0.f;
        g_ncur[i] = g_noff[i];
    }
}

__global__ void fill_kernel(const void* ni, const void* ei, int nnz) {
    int i = blockIdx.x * blockDim.x + threadIdx.x;
    if (i >= nnz) return;
    int is64 = g_idx64;
    int n = load_idx(ni, i, is64);
    int e = load_idx(ei, i, is64);
    g_e_members[atomicAdd(&g_ecur[e], 1)] = n;
    g_n_members[atomicAdd(&g_ncur[n], 1)] = e;
}

// ---------------- GEMM1: tensor-core tf32 (3-pass compensated) ----------------
__device__ __forceinline__ void split_tf32(float x, unsigned& hi, unsigned& lo) {
    asm("cvt.rna.tf32.f32 %0, %1;" : "=r"(hi) : "f"(x));
    float r = x - __uint_as_float(hi);
    asm("cvt.rna.tf32.f32 %0, %1;" : "=r"(lo) : "f"(r));
}

__device__ __forceinline__ void mma_tf32(float* c, unsigned a0, unsigned a1,
                                         unsigned a2, unsigned a3,
                                         unsigned b0, unsigned b1) {
    asm("mma.sync.aligned.m16n8k8.row.col.f32.tf32.tf32.f32 "
        "{%0,%1,%2,%3}, {%4,%5,%6,%7}, {%8,%9}, {%0,%1,%2,%3};"
        : "+f"(c[0]), "+f"(c[1]), "+f"(c[2]), "+f"(c[3])
        : "r"(a0), "r"(a1), "r"(a2), "r"(a3), "r"(b0), "r"(b1));
}

// block: 128 M x 128 N, 512 threads (16 warps, 4x4), warp tile 32x32
// K chunked by 16; A split into tf32 hi/lo, W split into hi/lo.
__global__ __launch_bounds__(512) void gemm1_tf32(const float* __restrict__ A,
                                                  const float* __restrict__ W, int M) {
    __shared__ unsigned Ah[128][20], Al[128][20];   // [m][k], pad->stride 20
    __shared__ unsigned Bh[16][132], Bl[16][132];   // [k][n], pad->stride 132
    const int tid  = threadIdx.x;
    const int wid  = tid >> 5, lane = tid & 31;
    const int g = lane >> 2, t = lane & 3;
    const int wm = (wid >> 2) * 32;
    const int wn = (wid & 3) * 32;
    const int mbase = blockIdx.x * 128;

    float acc[2][4][4];
#pragma unroll
    for (int a = 0; a < 2; a++)
#pragma unroll
        for (int b = 0; b < 4; b++)
#pragma unroll
            for (int c = 0; c < 4; c++) acc[a][b][c] = 0.f;

    const int ar  = tid >> 2;          // 0..127 (A stage row)
    const int ac4 = tid & 3;           // 4 float4 per A row chunk
    const int br  = tid >> 5;          // 0..15  (B stage row)
    const int bc4 = tid & 31;          // 32 float4 per B row
    const bool avalid = (mbase + ar) < M;
    const float* Arow = A + (size_t)(mbase + ar) * 128;

    for (int kc = 0; kc < 128; kc += 16) {
        float4 av = avalid ? *(const float4*)(Arow + kc + ac4 * 4)
                           : make_float4(0.f, 0.f, 0.f, 0.f);
        float4 bv = *(const float4*)(W + (size_t)(kc + br) * 128 + bc4 * 4);
        unsigned h, l;
        split_tf32(av.x, h, l); Ah[ar][ac4 * 4 + 0] = h; Al[ar][ac4 * 4 + 0] = l;
        split_tf32(av.y, h, l); Ah[ar][ac4 * 4 + 1] = h; Al[ar][ac4 * 4 + 1] = l;
        split_tf32(av.z, h, l); Ah[ar][ac4 * 4 + 2] = h; Al[ar][ac4 * 4 + 2] = l;
        split_tf32(av.w, h, l); Ah[ar][ac4 * 4 + 3] = h; Al[ar][ac4 * 4 + 3] = l;
        split_tf32(bv.x, h, l); Bh[br][bc4 * 4 + 0] = h; Bl[br][bc4 * 4 + 0] = l;
        split_tf32(bv.y, h, l); Bh[br][bc4 * 4 + 1] = h; Bl[br][bc4 * 4 + 1] = l;
        split_tf32(bv.z, h, l); Bh[br][bc4 * 4 + 2] = h; Bl[br][bc4 * 4 + 2] = l;
        split_tf32(bv.w, h, l); Bh[br][bc4 * 4 + 3] = h; Bl[br][bc4 * 4 + 3] = l;
        __syncthreads();

#pragma unroll
        for (int ks = 0; ks < 2; ks++) {
            const int k0 = ks * 8;
            unsigned bh[4][2], bl[4][2];
#pragma unroll
            for (int nt = 0; nt < 4; nt++) {
                int cn = wn + nt * 8 + g;
                bh[nt][0] = Bh[k0 + t][cn];
                bh[nt][1] = Bh[k0 + t + 4][cn];
                bl[nt][0] = Bl[k0 + t][cn];
                bl[nt][1] = Bl[k0 + t + 4][cn];
            }
#pragma unroll
            for (int mt = 0; mt < 2; mt++) {
                const int rm = wm + mt * 16;
                unsigned ah0 = Ah[rm + g][k0 + t];
                unsigned ah1 = Ah[rm + g + 8][k0 + t];
                unsigned ah2 = Ah[rm + g][k0 + t + 4];
                unsigned ah3 = Ah[rm + g + 8][k0 + t + 4];
                unsigned al0 = Al[rm + g][k0 + t];
                unsigned al1 = Al[rm + g + 8][k0 + t];
                unsigned al2 = Al[rm + g][k0 + t + 4];
                unsigned al3 = Al[rm + g + 8][k0 + t + 4];
#pragma unroll
                for (int nt = 0; nt < 4; nt++) {
                    mma_tf32(acc[mt][nt], ah0, ah1, ah2, ah3, bh[nt][0], bh[nt][1]);
                    mma_tf32(acc[mt][nt], ah0, ah1, ah2, ah3, bl[nt][0], bl[nt][1]);
                    mma_tf32(acc[mt][nt], al0, al1, al2, al3, bh[nt][0], bh[nt][1]);
                }
            }
        }
        __syncthreads();
    }

#pragma unroll
    for (int mt = 0; mt < 2; mt++) {
#pragma unroll
        for (int nt = 0; nt < 4; nt++) {
            int row = mbase + wm + mt * 16 + g;
            int col = wn + nt * 8 + 2 * t;
            if (row < M)
                *(float2*)&g_xw[(size_t)row * 128 + col] =
                    make_float2(acc[mt][nt][0], acc[mt][nt][1]);
            if (row + 8 < M)
                *(float2*)&g_xw[(size_t)(row + 8) * 128 + col] =
                    make_float2(acc[mt][nt][2], acc[mt][nt][3]);
        }
    }
}

// ---------------- GEMM2: [M,128] @ [128,16] -> g_hw ----------------
__global__ __launch_bounds__(256) void gemm2_kernel(const float* __restrict__ W, int M) {
    __shared__ float hs[64][132];
    __shared__ float ws[128 * 16];
    const int tid = threadIdx.x;
#pragma unroll
    for (int i = 0; i < 8; i++) ws[tid + i * 256] = W[tid + i * 256];
    const int row0 = blockIdx.x * 64;
#pragma unroll
    for (int i = 0; i < 8; i++) {
        int idx = tid + i * 256;          // 0..2047 float4 slots
        int r = idx >> 5;                 // 32 f4 per row
        int c4 = idx & 31;
        int gr = row0 + r;
        float4 v = (gr < M) ? *(const float4*)&g_h[(size_t)gr * 128 + c4 * 4]
                            : make_float4(0.f, 0.f, 0.f, 0.f);
        *(float4*)&hs[r][c4 * 4] = v;
    }
    __syncthreads();
    const int r = tid >> 2, c4 = tid & 3;
    float4 acc = make_float4(0.f, 0.f, 0.f, 0.f);
#pragma unroll 4
    for (int k = 0; k < 128; k++) {
        float hv = hs[r][k];
        float4 w4 = *(const float4*)&ws[k * 16 + c4 * 4];
        acc.x += hv * w4.x; acc.y += hv * w4.y;
        acc.z += hv * w4.z; acc.w += hv * w4.w;
    }
    int gr = row0 + r;
    if (gr < M) *(float4*)&g_hw[(size_t)gr * 16 + c4 * 4] = acc;
}

// ---------------- gather-reduce, F = 128 (warp per destination row) ----------------
template <bool RELU>
__global__ void gather128(const float* __restrict__ src, float* __restrict__ dst,
                          const int* __restrict__ mem, const int* __restrict__ off,
                          const float* __restrict__ inv, const float* __restrict__ bias,
                          int nrows) {
    int w = (blockIdx.x * blockDim.x + threadIdx.x) >> 5;
    int lane = threadIdx.x & 31;
    if (w >= nrows) return;
    int beg = off[w], end = off[w + 1];
    float4 a0 = make_float4(0.f, 0.f, 0.f, 0.f);
    float4 a1 = make_float4(0.f, 0.f, 0.f, 0.f);
    int j = beg;
    for (; j + 1 < end; j += 2) {
        int m0 = mem[j], m1 = mem[j + 1];
        float4 v0 = *(const float4*)&src[(size_t)m0 * F1 + lane * 4];
        float4 v1 = *(const float4*)&src[(size_t)m1 * F1 + lane * 4];
        a0.x += v0.x; a0.y += v0.y; a0.z += v0.z; a0.w += v0.w;
        a1.x += v1.x; a1.y += v1.y; a1.z += v1.z; a1.w += v1.w;
    }
    if (j < end) {
        int m0 = mem[j];
        float4 v0 = *(const float4*)&src[(size_t)m0 * F1 + lane * 4];
        a0.x += v0.x; a0.y += v0.y; a0.z += v0.z; a0.w += v0.w;
    }
    float s = inv[w];
    float4 r = make_float4((a0.x + a1.x) * s, (a0.y + a1.y) * s,
                           (a0.z + a1.z) * s, (a0.w + a1.w) * s);
    if (bias) {
        float4 b = *(const float4*)&bias[lane * 4];
        r.x += b.x; r.y += b.y; r.z += b.z; r.w += b.w;
    }
    if (RELU) {
        r.x = fmaxf(r.x, 0.f); r.y = fmaxf(r.y, 0.f);
        r.z = fmaxf(r.z, 0.f); r.w = fmaxf(r.w, 0.f);
    }
    *(float4*)&dst[(size_t)w * F1 + lane * 4] = r;
}

// ---------------- gather-reduce, F = 16 (warp per row, 2 members/iter) --------------
__global__ void gather16(const float* __restrict__ src, float* __restrict__ dst,
                         const int* __restrict__ mem, const int* __restrict__ off,
                         const float* __restrict__ inv, const float* __restrict__ bias,
                         int nrows) {
    int w = (blockIdx.x * blockDim.x + threadIdx.x) >> 5;
    int lane = threadIdx.x & 31;
    if (w >= nrows) return;
    int beg = off[w], end = off[w + 1];
    int half = lane >> 4, f = lane & 15;
    float acc = 0.f;
    for (int j = beg + half; j < end; j += 2)
        acc += src[(size_t)mem[j] * F2 + f];
    acc += __shfl_down_sync(0xffffffffu, acc, 16);
    if (lane < 16) {
        float r = acc * inv[w];
        if (bias) r += bias[f];
        dst[(size_t)w * F2 + f] = r;
    }
}

// ---------------- launcher ----------------
extern "C" void kernel_launch(void* const* d_in, const int* in_sizes, int n_in,
                              void* d_out, int out_size) {
    const float* x  = (const float*)d_in[0];
    const void*  ni = d_in[1];
    const void*  ei = d_in[2];
    const float* W1 = (const float*)d_in[n_in - 4];
    const float* b1 = (const float*)d_in[n_in - 3];
    const float* W2 = (const float*)d_in[n_in - 2];
    const float* b2 = (const float*)d_in[n_in - 1];
    const int nnz = in_sizes[1];
    const int M   = in_sizes[0] / F1;
    float* out = (float*)d_out;

    static bool  s_init = false;
    static cudaStream_t s2;
    static cudaEvent_t ev0, ev1;
    static int*   p_ecnt, *p_eoff, *p_ncnt, *p_noff, *p_bs, *p_emem, *p_nmem;
    static float* p_binv, *p_dinv, *p_xw, *p_ef, *p_h, *p_hw, *p_ef2;
    if (!s_init) {
        cudaGetSymbolAddress((void**)&p_ecnt, g_ecnt);
        cudaGetSymbolAddress((void**)&p_eoff, g_eoff);
        cudaGetSymbolAddress((void**)&p_ncnt, g_ncnt);
        cudaGetSymbolAddress((void**)&p_noff, g_noff);
        cudaGetSymbolAddress((void**)&p_bs,   g_bsums);
        cudaGetSymbolAddress((void**)&p_emem, g_e_members);
        cudaGetSymbolAddress((void**)&p_nmem, g_n_members);
        cudaGetSymbolAddress((void**)&p_binv, g_binv);
        cudaGetSymbolAddress((void**)&p_dinv, g_dinv);
        cudaGetSymbolAddress((void**)&p_xw,   g_xw);
        cudaGetSymbolAddress((void**)&p_ef,   g_efeat);
        cudaGetSymbolAddress((void**)&p_h,    g_h);
        cudaGetSymbolAddress((void**)&p_hw,   g_hw);
        cudaGetSymbolAddress((void**)&p_ef2,  g_efeat2);
        cudaStreamCreateWithFlags(&s2, cudaStreamNonBlocking);
        cudaEventCreateWithFlags(&ev0, cudaEventDisableTiming);
        cudaEventCreateWithFlags(&ev1, cudaEventDisableTiming);
        s_init = true;
    }

    // ---- fork: GEMM1 (depends only on x, W1) runs on s2, concurrent with CSR build
    cudaEventRecord(ev0, 0);
    cudaStreamWaitEvent(s2, ev0, 0);
    gemm1_tf32<<<(M + 127) / 128, 512, 0, s2>>>(x, W1, M);
    cudaEventRecord(ev1, s2);

    // ---- CSR build on default stream
    detect_kernel<<<1, 64>>>(ni, nnz);
    zero_cnt_kernel<<<(N_NODES_C + 255) / 256, 256>>>();
    hist_kernel<<<(nnz + 255) / 256, 256>>>(ni, ei, nnz);

    block_sums_kernel<<<NB_EDGES, SCAN_B>>>(p_ecnt, N_EDGES_C, p_bs);
    scan_bsums_kernel<<<1, SCAN_B>>>(p_bs, NB_EDGES);
    scan_apply_kernel<<<NB_EDGES, SCAN_B>>>(p_ecnt, N_EDGES_C, p_bs, p_eoff);
    block_sums_kernel<<<NB_NODES, SCAN_B>>>(p_ncnt, N_NODES_C, p_bs);
    scan_bsums_kernel<<<1, SCAN_B>>>(p_bs, NB_NODES);
    scan_apply_kernel<<<NB_NODES, SCAN_B>>>(p_ncnt, N_NODES_C, p_bs, p_noff);

    prep_kernel<<<(N_NODES_C + 255) / 256, 256>>>();
    fill_kernel<<<(nnz + 255) / 256, 256>>>(ni, ei, nnz);

    // ---- join: gathers need both CSR (stream 0) and GEMM1 (s2)
    cudaStreamWaitEvent(0, ev1, 0);

    // layer 1: node -> edge (Binv), then edge -> node (Dinv, +b1, relu)
    {
        int blocks_e = (N_EDGES_C * 32 + 255) / 256;
        int blocks_n = (N_NODES_C * 32 + 255) / 256;
        gather128<false><<<blocks_e, 256>>>(p_xw, p_ef, p_emem, p_eoff, p_binv, nullptr, N_EDGES_C);
        gather128<true ><<<blocks_n, 256>>>(p_ef, p_h,  p_nmem, p_noff, p_dinv, b1,      N_NODES_C);
    }

    gemm2_kernel<<<(M + 63) / 64, 256>>>(W2, M);

    // layer 2
    {
        int blocks_e = (N_EDGES_C * 32 + 255) / 256;
        int blocks_n = (N_NODES_C * 32 + 255) / 256;
        gather16<<<blocks_e, 256>>>(p_hw,  p_ef2, p_emem, p_eoff, p_binv, nullptr, N_EDGES_C);
        gather16<<<blocks_n, 256>>>(p_ef2, out,   p_nmem, p_noff, p_dinv, b2,      N_NODES_C);
    }
}